// round 7
// baseline (speedup 1.0000x reference)
#include <cuda_runtime.h>
#include <cuda_bf16.h>
#include <cstdint>

#define N_NODES 100000
#define N_EDGES 1600000
#define D 128
#define EPS 1e-5f

// ---------------- scratch ----------------
__device__ float g_aggr[(size_t)N_NODES * D];
__device__ float g_h[(size_t)N_NODES * D];
__device__ float g_sum[D];
__device__ float g_sumsq[D];
__device__ int   g_idx_is64;
__device__ __nv_bfloat16 gW_hi[256 * 128];   // rows 0-127 W_root, 128-255 W_rel
__device__ __nv_bfloat16 gW_lo[256 * 128];

// ---------------- helpers ----------------
__device__ __forceinline__ uint32_t smem_u32(const void* p) {
    uint32_t a;
    asm("{ .reg .u64 t; cvta.to.shared.u64 t, %1; cvt.u32.u64 %0, t; }"
        : "=r"(a) : "l"(p));
    return a;
}
__device__ __forceinline__ void ldsm_x4_t(uint32_t& r0, uint32_t& r1,
                                          uint32_t& r2, uint32_t& r3, uint32_t a) {
    asm volatile("ldmatrix.sync.aligned.m8n8.x4.trans.shared.b16 {%0,%1,%2,%3}, [%4];"
                 : "=r"(r0), "=r"(r1), "=r"(r2), "=r"(r3) : "r"(a));
}
__device__ __forceinline__ void mma_bf16(float* c, const uint32_t* a, const uint32_t* b) {
    asm volatile("mma.sync.aligned.m16n8k16.row.col.f32.bf16.bf16.f32 "
                 "{%0,%1,%2,%3}, {%4,%5,%6,%7}, {%8,%9}, {%0,%1,%2,%3};"
                 : "+f"(c[0]), "+f"(c[1]), "+f"(c[2]), "+f"(c[3])
                 : "r"(a[0]), "r"(a[1]), "r"(a[2]), "r"(a[3]),
                   "r"(b[0]), "r"(b[1]));
}
__device__ __forceinline__ void split_bf(float2 v, uint32_t& hi, uint32_t& lo) {
    __nv_bfloat16 h0 = __float2bfloat16(v.x);
    __nv_bfloat16 h1 = __float2bfloat16(v.y);
    __nv_bfloat162 hp = __halves2bfloat162(h0, h1);
    __nv_bfloat162 lp = __halves2bfloat162(
        __float2bfloat16(v.x - __bfloat162float(h0)),
        __float2bfloat16(v.y - __bfloat162float(h1)));
    hi = *(uint32_t*)&hp;
    lo = *(uint32_t*)&lp;
}
__device__ __forceinline__ void red_add_v4(float* addr, float4 v) {
    asm volatile("red.global.add.v4.f32 [%0], {%1, %2, %3, %4};"
                 :: "l"(addr), "f"(v.x), "f"(v.y), "f"(v.z), "f"(v.w)
                 : "memory");
}

// smem layout (byte offsets in dynamic smem)
#define B_HI   0             // 128 rows * 272 B
#define B_LO   34816
#define SM_BIAS 69632        // 128 f32
#define SM_SSUM 70144        // 128 f32
#define SM_SSQ  70656        // 128 f32
#define SMEMSZ  71168

// ---------------- kernel 0: detect edge_index dtype ----------------
__global__ void probe_kernel(const int* __restrict__ e) {
    __shared__ int nz;
    if (threadIdx.x == 0) nz = 0;
    __syncthreads();
    int v = e[threadIdx.x * 2 + 1];
    if (v != 0) atomicAdd(&nz, 1);
    __syncthreads();
    if (threadIdx.x == 0) g_idx_is64 = (nz == 0) ? 1 : 0;
}

// ---------------- kernel 1: zero aggr + stats ----------------
__global__ void zero_kernel() {
    int idx = blockIdx.x * blockDim.x + threadIdx.x;
    const int n4 = (N_NODES * D) / 4;
    if (idx < n4) ((float4*)g_aggr)[idx] = make_float4(0.f, 0.f, 0.f, 0.f);
    if (blockIdx.x == 0 && threadIdx.x < D) {
        g_sum[threadIdx.x] = 0.f;
        g_sumsq[threadIdx.x] = 0.f;
    }
}

// ---------------- kernel 2: convert weights to bf16 hi/lo (once) ----------
__global__ void wconv_kernel(const float* __restrict__ W_root,
                             const float* __restrict__ W_rel) {
    int idx = blockIdx.x * blockDim.x + threadIdx.x;   // 8192 threads
#pragma unroll
    for (int p = idx; p < 16384; p += 8192) {
        int k = p >> 6;
        int n2 = (p & 63) * 2;
        const float* W = (k < 128) ? (W_root + k * 128 + n2)
                                   : (W_rel + (k - 128) * 128 + n2);
        float2 v = *(const float2*)W;
        uint32_t hi, lo;
        split_bf(v, hi, lo);
        *(uint32_t*)((char*)gW_hi + (size_t)(k * 128 + n2) * 2) = hi;
        *(uint32_t*)((char*)gW_lo + (size_t)(k * 128 + n2) * 2) = lo;
    }
}

// ---------------- shared GEMM body ----------------
// 256 threads = 8 warps; warp w handles rows m0+w*16 .. +16, all 128 cols.
// A: fp32 loaded direct from global into mma fragment layout, hi/lo split in regs.
// B: bf16 hi/lo resident in smem for all K=128 (one fill, one sync).
template<int PHASE>   // 0: h = x@W_root (raw); 1: h += aggr@W_rel + bias, + stats
__device__ __forceinline__ void gemm_body(const float* __restrict__ A,
                                          const float* __restrict__ bias,
                                          char* smem, uint32_t sb, int blk) {
    const int tid = threadIdx.x;
    const int w = tid >> 5;
    const int lid = tid & 31;
    const int m0 = blk * 128;

    // fill B smem: 2048 16B chunks each for hi and lo
#pragma unroll
    for (int i = 0; i < 8; i++) {
        int ch = tid + i * 256;
        int row = ch >> 4, c16 = ch & 15;
        size_t gsrc = (size_t)((PHASE * 128 + row) * 128 + c16 * 8) * 2;
        *(uint4*)(smem + B_HI + row * 272 + c16 * 16) = *(const uint4*)((const char*)gW_hi + gsrc);
        *(uint4*)(smem + B_LO + row * 272 + c16 * 16) = *(const uint4*)((const char*)gW_lo + gsrc);
    }
    if (PHASE == 1 && tid < 128) {
        ((float*)(smem + SM_BIAS))[tid] = bias[tid];
        ((float*)(smem + SM_SSUM))[tid] = 0.f;
        ((float*)(smem + SM_SSQ))[tid]  = 0.f;
    }
    __syncthreads();

    float acc[16][4];
#pragma unroll
    for (int q = 0; q < 16; q++)
#pragma unroll
        for (int c = 0; c < 4; c++) acc[q][c] = 0.f;

    const int r = lid >> 2;
    const int cq = (lid & 3) * 2;
    const int m = m0 + w * 16 + r;
    const bool v0 = m < N_NODES;
    const bool v1 = (m + 8) < N_NODES;
    const float* pr0 = A + (size_t)m * D + cq;
    const float* pr1 = A + (size_t)(m + 8) * D + cq;
    const float2 fz = make_float2(0.f, 0.f);

#pragma unroll
    for (int s = 0; s < 8; s++) {          // K = 128, 8 k16 steps
        const int ko = s * 16;
        float2 x00 = v0 ? *(const float2*)(pr0 + ko) : fz;
        float2 x10 = v1 ? *(const float2*)(pr1 + ko) : fz;
        float2 x01 = v0 ? *(const float2*)(pr0 + ko + 8) : fz;
        float2 x11 = v1 ? *(const float2*)(pr1 + ko + 8) : fz;
        uint32_t ah[4], al[4];
        split_bf(x00, ah[0], al[0]);
        split_bf(x10, ah[1], al[1]);
        split_bf(x01, ah[2], al[2]);
        split_bf(x11, ah[3], al[3]);

        const uint32_t rowa = sb + (uint32_t)((s * 16 + (lid & 15)) * 272 + (lid >> 4) * 16);
#pragma unroll
        for (int q8 = 0; q8 < 8; q8++) {   // 16-col blocks
            uint32_t bh[4], bl[4];
            uint32_t ba = rowa + (uint32_t)(q8 * 32);
            ldsm_x4_t(bh[0], bh[1], bh[2], bh[3], ba + B_HI);
            ldsm_x4_t(bl[0], bl[1], bl[2], bl[3], ba + B_LO);
            float* c0 = acc[q8 * 2];
            float* c1 = acc[q8 * 2 + 1];
            mma_bf16(c0, ah, bh);
            mma_bf16(c0, ah, bl);
            mma_bf16(c0, al, bh);
            mma_bf16(c1, ah, bh + 2);
            mma_bf16(c1, ah, bl + 2);
            mma_bf16(c1, al, bh + 2);
        }
    }

    // epilogue
    const int n0 = cq;
    if (PHASE == 0) {
#pragma unroll
        for (int q = 0; q < 16; q++) {
            int n = q * 8 + n0;
            if (v0) *(float2*)(g_h + (size_t)m * D + n) = make_float2(acc[q][0], acc[q][1]);
            if (v1) *(float2*)(g_h + (size_t)(m + 8) * D + n) = make_float2(acc[q][2], acc[q][3]);
        }
    } else {
        const float* bs = (const float*)(smem + SM_BIAS);
        float* ssum = (float*)(smem + SM_SSUM);
        float* ssq  = (float*)(smem + SM_SSQ);
#pragma unroll
        for (int q = 0; q < 16; q++) {
            int n = q * 8 + n0;
            float b0 = bs[n], b1 = bs[n + 1];
            float s0 = 0.f, s1 = 0.f, q0 = 0.f, q1 = 0.f;
            if (v0) {
                float2 o = *(const float2*)(g_h + (size_t)m * D + n);
                o.x += acc[q][0] + b0;
                o.y += acc[q][1] + b1;
                *(float2*)(g_h + (size_t)m * D + n) = o;
                s0 += o.x; s1 += o.y;
                q0 += o.x * o.x; q1 += o.y * o.y;
            }
            if (v1) {
                float2 o = *(const float2*)(g_h + (size_t)(m + 8) * D + n);
                o.x += acc[q][2] + b0;
                o.y += acc[q][3] + b1;
                *(float2*)(g_h + (size_t)(m + 8) * D + n) = o;
                s0 += o.x; s1 += o.y;
                q0 += o.x * o.x; q1 += o.y * o.y;
            }
            atomicAdd(&ssum[n],     s0);
            atomicAdd(&ssum[n + 1], s1);
            atomicAdd(&ssq[n],      q0);
            atomicAdd(&ssq[n + 1],  q1);
        }
        __syncthreads();
        if (tid < 128) {
            atomicAdd(&g_sum[tid],   ssum[tid]);
            atomicAdd(&g_sumsq[tid], ssq[tid]);
        }
    }
}

// ---------------- scatter body: 8-edge batches per warp iteration --------
#define NWARPS_SC 6256          // 782 blocks * 8 warps
#define EB 8                    // edges per batch

__device__ __forceinline__ void scatter_body(const void* __restrict__ edge_index,
                                             const float* __restrict__ x, int blk) {
    const int wid = threadIdx.x >> 5;
    const int lane = threadIdx.x & 31;
    const int wglob = blk * 8 + wid;
    const bool is64 = (g_idx_is64 != 0);

#pragma unroll 1
    for (int it = 0; it < 32; it++) {
        int e0 = (wglob + it * NWARPS_SC) * EB;
        if (e0 >= N_EDGES) break;
        int s[EB], d[EB];
        if (is64) {
            const long long* e = (const long long*)edge_index;
#pragma unroll
            for (int j = 0; j < EB; j++) {
                s[j] = (int)e[e0 + j];
                d[j] = (int)e[N_EDGES + e0 + j];
            }
        } else {
            const int* e = (const int*)edge_index;
            int4 sv0 = *(const int4*)(e + e0);
            int4 sv1 = *(const int4*)(e + e0 + 4);
            int4 dv0 = *(const int4*)(e + N_EDGES + e0);
            int4 dv1 = *(const int4*)(e + N_EDGES + e0 + 4);
            s[0] = sv0.x; s[1] = sv0.y; s[2] = sv0.z; s[3] = sv0.w;
            s[4] = sv1.x; s[5] = sv1.y; s[6] = sv1.z; s[7] = sv1.w;
            d[0] = dv0.x; d[1] = dv0.y; d[2] = dv0.z; d[3] = dv0.w;
            d[4] = dv1.x; d[5] = dv1.y; d[6] = dv1.z; d[7] = dv1.w;
        }
        int cnt = N_EDGES - e0; if (cnt > EB) cnt = EB;
        float4 v[EB];
#pragma unroll
        for (int j = 0; j < EB; j++) {
            bool ok = (j < cnt) && ((unsigned)s[j] < N_NODES);
            v[j] = ok ? ((const float4*)(x + (size_t)s[j] * D))[lane]
                      : make_float4(0.f, 0.f, 0.f, 0.f);
        }
#pragma unroll
        for (int j = 0; j < EB; j++) {
            if ((j < cnt) && ((unsigned)s[j] < N_NODES) && ((unsigned)d[j] < N_NODES))
                red_add_v4(g_aggr + (size_t)d[j] * D + lane * 4, v[j]);
        }
    }
}

// ---------------- phase A: heterogeneous scatter || x@W_root ----------------
__global__ void __launch_bounds__(256, 2)
hetA_kernel(const float* __restrict__ x, const void* __restrict__ eidx) {
    extern __shared__ char smem[];
    int id = blockIdx.x >> 1;
    if (blockIdx.x & 1) {
        scatter_body(eidx, x, id);
    } else {
        gemm_body<0>(x, nullptr, smem, smem_u32(smem), id);
    }
}

// ---------------- phase B: aggr@W_rel + bias + stats, accumulate ----------
__global__ void __launch_bounds__(256, 2)
gemmB_kernel(const float* __restrict__ b_rel) {
    extern __shared__ char smem[];
    gemm_body<1>(g_aggr, b_rel, smem, smem_u32(smem), blockIdx.x);
}

// ---------------- fused finalize + normalize + ReLU ----------------
__global__ void norm_kernel(const float* __restrict__ gamma,
                            const float* __restrict__ beta,
                            float* __restrict__ out) {
    __shared__ float ssc[D], ssh[D];
    int t = threadIdx.x;
    if (t < D) {
        float inv_n = 1.0f / (float)N_NODES;
        float mean = g_sum[t] * inv_n;
        float var = g_sumsq[t] * inv_n - mean * mean;
        float sc = gamma[t] * rsqrtf(var + EPS);
        ssc[t] = sc;
        ssh[t] = beta[t] - mean * sc;
    }
    __syncthreads();
    int idx = blockIdx.x * blockDim.x + t;
    const int n4 = (N_NODES * D) / 4;
    if (idx >= n4) return;
    int c4 = (idx & (D / 4 - 1)) * 4;
    float4 h = ((const float4*)g_h)[idx];
    float4 o;
    o.x = fmaxf(h.x * ssc[c4 + 0] + ssh[c4 + 0], 0.f);
    o.y = fmaxf(h.y * ssc[c4 + 1] + ssh[c4 + 1], 0.f);
    o.z = fmaxf(h.z * ssc[c4 + 2] + ssh[c4 + 2], 0.f);
    o.w = fmaxf(h.w * ssc[c4 + 3] + ssh[c4 + 3], 0.f);
    ((float4*)out)[idx] = o;
}

// ---------------- launch ----------------
extern "C" void kernel_launch(void* const* d_in, const int* in_sizes, int n_in,
                              void* d_out, int out_size) {
    const float* x      = (const float*)d_in[0];
    const void*  eidx   = d_in[1];
    const float* W_root = (const float*)d_in[2];
    const float* W_rel  = (const float*)d_in[3];
    const float* b_rel  = (const float*)d_in[4];
    const float* gamma  = (const float*)d_in[5];
    const float* beta   = (const float*)d_in[6];
    float*       out    = (float*)d_out;

    cudaFuncSetAttribute(hetA_kernel,
                         cudaFuncAttributeMaxDynamicSharedMemorySize, SMEMSZ);
    cudaFuncSetAttribute(gemmB_kernel,
                         cudaFuncAttributeMaxDynamicSharedMemorySize, SMEMSZ);

    probe_kernel<<<1, 64>>>((const int*)eidx);

    const int n4 = (N_NODES * D) / 4;
    zero_kernel<<<(n4 + 255) / 256, 256>>>();

    wconv_kernel<<<32, 256>>>(W_root, W_rel);

    hetA_kernel<<<1564, 256, SMEMSZ>>>(x, eidx);

    gemmB_kernel<<<782, 256, SMEMSZ>>>(b_rel);

    norm_kernel<<<(n4 + 255) / 256, 256>>>(gamma, beta, out);
}

// round 8
// speedup vs baseline: 1.2725x; 1.2725x over previous
#include <cuda_runtime.h>
#include <cuda_bf16.h>
#include <cstdint>

#define N_NODES 100000
#define N_EDGES 1600000
#define D 128
#define EPS 1e-5f

// ---------------- scratch ----------------
__device__ float g_aggr[(size_t)N_NODES * D];
__device__ float g_h[(size_t)N_NODES * D];
__device__ float g_sum[D];
__device__ float g_sumsq[D];
__device__ int   g_idx_is64;
__device__ __nv_bfloat16 gW_hi[256 * 128];   // rows 0-127 W_root, 128-255 W_rel
__device__ __nv_bfloat16 gW_lo[256 * 128];

// ---------------- helpers ----------------
__device__ __forceinline__ uint32_t smem_u32(const void* p) {
    uint32_t a;
    asm("{ .reg .u64 t; cvta.to.shared.u64 t, %1; cvt.u32.u64 %0, t; }"
        : "=r"(a) : "l"(p));
    return a;
}
__device__ __forceinline__ void ldsm_x4_t(uint32_t& r0, uint32_t& r1,
                                          uint32_t& r2, uint32_t& r3, uint32_t a) {
    asm volatile("ldmatrix.sync.aligned.m8n8.x4.trans.shared.b16 {%0,%1,%2,%3}, [%4];"
                 : "=r"(r0), "=r"(r1), "=r"(r2), "=r"(r3) : "r"(a));
}
__device__ __forceinline__ void mma_bf16(float* c, const uint32_t* a, const uint32_t* b) {
    asm volatile("mma.sync.aligned.m16n8k16.row.col.f32.bf16.bf16.f32 "
                 "{%0,%1,%2,%3}, {%4,%5,%6,%7}, {%8,%9}, {%0,%1,%2,%3};"
                 : "+f"(c[0]), "+f"(c[1]), "+f"(c[2]), "+f"(c[3])
                 : "r"(a[0]), "r"(a[1]), "r"(a[2]), "r"(a[3]),
                   "r"(b[0]), "r"(b[1]));
}
__device__ __forceinline__ void split_bf(float2 v, uint32_t& hi, uint32_t& lo) {
    __nv_bfloat16 h0 = __float2bfloat16(v.x);
    __nv_bfloat16 h1 = __float2bfloat16(v.y);
    __nv_bfloat162 hp = __halves2bfloat162(h0, h1);
    __nv_bfloat162 lp = __halves2bfloat162(
        __float2bfloat16(v.x - __bfloat162float(h0)),
        __float2bfloat16(v.y - __bfloat162float(h1)));
    hi = *(uint32_t*)&hp;
    lo = *(uint32_t*)&lp;
}
__device__ __forceinline__ void red_add_v4(float* addr, float4 v) {
    asm volatile("red.global.add.v4.f32 [%0], {%1, %2, %3, %4};"
                 :: "l"(addr), "f"(v.x), "f"(v.y), "f"(v.z), "f"(v.w)
                 : "memory");
}

// smem layout (byte offsets in dynamic smem)
#define B_HI   0             // 128 rows * 272 B
#define B_LO   34816
#define SM_BIAS 69632        // 128 f32
#define SM_SSUM 70144        // 128 f32
#define SM_SSQ  70656        // 128 f32
#define SMEMSZ  71168

// ---------------- kernel 0: detect edge_index dtype ----------------
__global__ void probe_kernel(const int* __restrict__ e) {
    __shared__ int nz;
    if (threadIdx.x == 0) nz = 0;
    __syncthreads();
    int v = e[threadIdx.x * 2 + 1];
    if (v != 0) atomicAdd(&nz, 1);
    __syncthreads();
    if (threadIdx.x == 0) g_idx_is64 = (nz == 0) ? 1 : 0;
}

// ---------------- kernel 1: zero aggr + stats ----------------
__global__ void zero_kernel() {
    int idx = blockIdx.x * blockDim.x + threadIdx.x;
    const int n4 = (N_NODES * D) / 4;
    if (idx < n4) ((float4*)g_aggr)[idx] = make_float4(0.f, 0.f, 0.f, 0.f);
    if (blockIdx.x == 0 && threadIdx.x < D) {
        g_sum[threadIdx.x] = 0.f;
        g_sumsq[threadIdx.x] = 0.f;
    }
}

// ---------------- kernel 2: convert weights to bf16 hi/lo (once) ----------
__global__ void wconv_kernel(const float* __restrict__ W_root,
                             const float* __restrict__ W_rel) {
    int idx = blockIdx.x * blockDim.x + threadIdx.x;   // 8192 threads
#pragma unroll
    for (int p = idx; p < 16384; p += 8192) {
        int k = p >> 6;
        int n2 = (p & 63) * 2;
        const float* W = (k < 128) ? (W_root + k * 128 + n2)
                                   : (W_rel + (k - 128) * 128 + n2);
        float2 v = *(const float2*)W;
        uint32_t hi, lo;
        split_bf(v, hi, lo);
        *(uint32_t*)((char*)gW_hi + (size_t)(k * 128 + n2) * 2) = hi;
        *(uint32_t*)((char*)gW_lo + (size_t)(k * 128 + n2) * 2) = lo;
    }
}

// ---------------- shared GEMM body ----------------
template<int PHASE>   // 0: h = x@W_root (raw); 1: h += aggr@W_rel + bias, + stats
__device__ __forceinline__ void gemm_body(const float* __restrict__ A,
                                          const float* __restrict__ bias,
                                          char* smem, uint32_t sb, int blk) {
    const int tid = threadIdx.x;
    const int w = tid >> 5;
    const int lid = tid & 31;
    const int m0 = blk * 128;

    // fill B smem: 2048 16B chunks each for hi and lo
#pragma unroll
    for (int i = 0; i < 8; i++) {
        int ch = tid + i * 256;
        int row = ch >> 4, c16 = ch & 15;
        size_t gsrc = (size_t)((PHASE * 128 + row) * 128 + c16 * 8) * 2;
        *(uint4*)(smem + B_HI + row * 272 + c16 * 16) = *(const uint4*)((const char*)gW_hi + gsrc);
        *(uint4*)(smem + B_LO + row * 272 + c16 * 16) = *(const uint4*)((const char*)gW_lo + gsrc);
    }
    if (PHASE == 1 && tid < 128) {
        ((float*)(smem + SM_BIAS))[tid] = bias[tid];
        ((float*)(smem + SM_SSUM))[tid] = 0.f;
        ((float*)(smem + SM_SSQ))[tid]  = 0.f;
    }
    __syncthreads();

    float acc[16][4];
#pragma unroll
    for (int q = 0; q < 16; q++)
#pragma unroll
        for (int c = 0; c < 4; c++) acc[q][c] = 0.f;

    const int r = lid >> 2;
    const int cq = (lid & 3) * 2;
    const int m = m0 + w * 16 + r;
    const bool v0 = m < N_NODES;
    const bool v1 = (m + 8) < N_NODES;
    const float* pr0 = A + (size_t)m * D + cq;
    const float* pr1 = A + (size_t)(m + 8) * D + cq;
    const float2 fz = make_float2(0.f, 0.f);

#pragma unroll
    for (int s = 0; s < 8; s++) {          // K = 128, 8 k16 steps
        const int ko = s * 16;
        float2 x00 = v0 ? *(const float2*)(pr0 + ko) : fz;
        float2 x10 = v1 ? *(const float2*)(pr1 + ko) : fz;
        float2 x01 = v0 ? *(const float2*)(pr0 + ko + 8) : fz;
        float2 x11 = v1 ? *(const float2*)(pr1 + ko + 8) : fz;
        uint32_t ah[4], al[4];
        split_bf(x00, ah[0], al[0]);
        split_bf(x10, ah[1], al[1]);
        split_bf(x01, ah[2], al[2]);
        split_bf(x11, ah[3], al[3]);

        const uint32_t rowa = sb + (uint32_t)((s * 16 + (lid & 15)) * 272 + (lid >> 4) * 16);
#pragma unroll
        for (int q8 = 0; q8 < 8; q8++) {   // 16-col blocks
            uint32_t bh[4], bl[4];
            uint32_t ba = rowa + (uint32_t)(q8 * 32);
            ldsm_x4_t(bh[0], bh[1], bh[2], bh[3], ba + B_HI);
            ldsm_x4_t(bl[0], bl[1], bl[2], bl[3], ba + B_LO);
            float* c0 = acc[q8 * 2];
            float* c1 = acc[q8 * 2 + 1];
            mma_bf16(c0, ah, bh);
            mma_bf16(c0, ah, bl);
            mma_bf16(c0, al, bh);
            mma_bf16(c1, ah, bh + 2);
            mma_bf16(c1, ah, bl + 2);
            mma_bf16(c1, al, bh + 2);
        }
    }

    // epilogue
    const int n0 = cq;
    if (PHASE == 0) {
#pragma unroll
        for (int q = 0; q < 16; q++) {
            int n = q * 8 + n0;
            if (v0) *(float2*)(g_h + (size_t)m * D + n) = make_float2(acc[q][0], acc[q][1]);
            if (v1) *(float2*)(g_h + (size_t)(m + 8) * D + n) = make_float2(acc[q][2], acc[q][3]);
        }
    } else {
        const float* bs = (const float*)(smem + SM_BIAS);
        float* ssum = (float*)(smem + SM_SSUM);
        float* ssq  = (float*)(smem + SM_SSQ);
#pragma unroll
        for (int q = 0; q < 16; q++) {
            int n = q * 8 + n0;
            float b0 = bs[n], b1 = bs[n + 1];
            float s0 = 0.f, s1 = 0.f, q0 = 0.f, q1 = 0.f;
            if (v0) {
                float2 o = *(const float2*)(g_h + (size_t)m * D + n);
                o.x += acc[q][0] + b0;
                o.y += acc[q][1] + b1;
                *(float2*)(g_h + (size_t)m * D + n) = o;
                s0 += o.x; s1 += o.y;
                q0 += o.x * o.x; q1 += o.y * o.y;
            }
            if (v1) {
                float2 o = *(const float2*)(g_h + (size_t)(m + 8) * D + n);
                o.x += acc[q][2] + b0;
                o.y += acc[q][3] + b1;
                *(float2*)(g_h + (size_t)(m + 8) * D + n) = o;
                s0 += o.x; s1 += o.y;
                q0 += o.x * o.x; q1 += o.y * o.y;
            }
            // column reduce across lanes sharing (lid & 3): xor over bits 2,3,4
#pragma unroll
            for (int mk = 4; mk <= 16; mk <<= 1) {
                s0 += __shfl_xor_sync(0xffffffffu, s0, mk);
                s1 += __shfl_xor_sync(0xffffffffu, s1, mk);
                q0 += __shfl_xor_sync(0xffffffffu, q0, mk);
                q1 += __shfl_xor_sync(0xffffffffu, q1, mk);
            }
            if ((lid >> 2) == 0) {
                atomicAdd(&ssum[n],     s0);
                atomicAdd(&ssum[n + 1], s1);
                atomicAdd(&ssq[n],      q0);
                atomicAdd(&ssq[n + 1],  q1);
            }
        }
        __syncthreads();
        if (tid < 128) {
            atomicAdd(&g_sum[tid],   ssum[tid]);
            atomicAdd(&g_sumsq[tid], ssq[tid]);
        }
    }
}

// ---------------- scatter body: 8-edge batches per warp iteration --------
#define NWARPS_SC 6256          // 782 blocks * 8 warps
#define EB 8                    // edges per batch

__device__ __forceinline__ void scatter_body(const void* __restrict__ edge_index,
                                             const float* __restrict__ x, int blk) {
    const int wid = threadIdx.x >> 5;
    const int lane = threadIdx.x & 31;
    const int wglob = blk * 8 + wid;
    const bool is64 = (g_idx_is64 != 0);

#pragma unroll 1
    for (int it = 0; it < 32; it++) {
        int e0 = (wglob + it * NWARPS_SC) * EB;
        if (e0 >= N_EDGES) break;
        int s[EB], d[EB];
        if (is64) {
            const long long* e = (const long long*)edge_index;
#pragma unroll
            for (int j = 0; j < EB; j++) {
                s[j] = (int)e[e0 + j];
                d[j] = (int)e[N_EDGES + e0 + j];
            }
        } else {
            const int* e = (const int*)edge_index;
            int4 sv0 = *(const int4*)(e + e0);
            int4 sv1 = *(const int4*)(e + e0 + 4);
            int4 dv0 = *(const int4*)(e + N_EDGES + e0);
            int4 dv1 = *(const int4*)(e + N_EDGES + e0 + 4);
            s[0] = sv0.x; s[1] = sv0.y; s[2] = sv0.z; s[3] = sv0.w;
            s[4] = sv1.x; s[5] = sv1.y; s[6] = sv1.z; s[7] = sv1.w;
            d[0] = dv0.x; d[1] = dv0.y; d[2] = dv0.z; d[3] = dv0.w;
            d[4] = dv1.x; d[5] = dv1.y; d[6] = dv1.z; d[7] = dv1.w;
        }
        int cnt = N_EDGES - e0; if (cnt > EB) cnt = EB;
        float4 v[EB];
#pragma unroll
        for (int j = 0; j < EB; j++) {
            bool ok = (j < cnt) && ((unsigned)s[j] < N_NODES);
            v[j] = ok ? ((const float4*)(x + (size_t)s[j] * D))[lane]
                      : make_float4(0.f, 0.f, 0.f, 0.f);
        }
#pragma unroll
        for (int j = 0; j < EB; j++) {
            if ((j < cnt) && ((unsigned)s[j] < N_NODES) && ((unsigned)d[j] < N_NODES))
                red_add_v4(g_aggr + (size_t)d[j] * D + lane * 4, v[j]);
        }
    }
}

// ---------------- phase A: heterogeneous scatter || x@W_root ----------------
__global__ void __launch_bounds__(256, 2)
hetA_kernel(const float* __restrict__ x, const void* __restrict__ eidx) {
    extern __shared__ char smem[];
    int id = blockIdx.x >> 1;
    if (blockIdx.x & 1) {
        scatter_body(eidx, x, id);
    } else {
        gemm_body<0>(x, nullptr, smem, smem_u32(smem), id);
    }
}

// ---------------- phase B: aggr@W_rel + bias + stats, accumulate ----------
__global__ void __launch_bounds__(256, 2)
gemmB_kernel(const float* __restrict__ b_rel) {
    extern __shared__ char smem[];
    gemm_body<1>(g_aggr, b_rel, smem, smem_u32(smem), blockIdx.x);
}

// ---------------- fused finalize + normalize + ReLU ----------------
__global__ void norm_kernel(const float* __restrict__ gamma,
                            const float* __restrict__ beta,
                            float* __restrict__ out) {
    __shared__ float ssc[D], ssh[D];
    int t = threadIdx.x;
    if (t < D) {
        float inv_n = 1.0f / (float)N_NODES;
        float mean = g_sum[t] * inv_n;
        float var = g_sumsq[t] * inv_n - mean * mean;
        float sc = gamma[t] * rsqrtf(var + EPS);
        ssc[t] = sc;
        ssh[t] = beta[t] - mean * sc;
    }
    __syncthreads();
    int idx = blockIdx.x * blockDim.x + t;
    const int n4 = (N_NODES * D) / 4;
    if (idx >= n4) return;
    int c4 = (idx & (D / 4 - 1)) * 4;
    float4 h = ((const float4*)g_h)[idx];
    float4 o;
    o.x = fmaxf(h.x * ssc[c4 + 0] + ssh[c4 + 0], 0.f);
    o.y = fmaxf(h.y * ssc[c4 + 1] + ssh[c4 + 1], 0.f);
    o.z = fmaxf(h.z * ssc[c4 + 2] + ssh[c4 + 2], 0.f);
    o.w = fmaxf(h.w * ssc[c4 + 3] + ssh[c4 + 3], 0.f);
    ((float4*)out)[idx] = o;
}

// ---------------- launch ----------------
extern "C" void kernel_launch(void* const* d_in, const int* in_sizes, int n_in,
                              void* d_out, int out_size) {
    const float* x      = (const float*)d_in[0];
    const void*  eidx   = d_in[1];
    const float* W_root = (const float*)d_in[2];
    const float* W_rel  = (const float*)d_in[3];
    const float* b_rel  = (const float*)d_in[4];
    const float* gamma  = (const float*)d_in[5];
    const float* beta   = (const float*)d_in[6];
    float*       out    = (float*)d_out;

    cudaFuncSetAttribute(hetA_kernel,
                         cudaFuncAttributeMaxDynamicSharedMemorySize, SMEMSZ);
    cudaFuncSetAttribute(gemmB_kernel,
                         cudaFuncAttributeMaxDynamicSharedMemorySize, SMEMSZ);

    probe_kernel<<<1, 64>>>((const int*)eidx);

    const int n4 = (N_NODES * D) / 4;
    zero_kernel<<<(n4 + 255) / 256, 256>>>();

    wconv_kernel<<<32, 256>>>(W_root, W_rel);

    hetA_kernel<<<1564, 256, SMEMSZ>>>(x, eidx);

    gemmB_kernel<<<782, 256, SMEMSZ>>>(b_rel);

    norm_kernel<<<(n4 + 255) / 256, 256>>>(gamma, beta, out);
}

// round 9
// speedup vs baseline: 1.3863x; 1.0894x over previous
#include <cuda_runtime.h>
#include <cuda_bf16.h>
#include <cstdint>

#define N_NODES 100000
#define N_EDGES 1600000
#define D 128
#define EPS 1e-5f

// ---------------- scratch ----------------
__device__ float g_aggr[(size_t)N_NODES * D];
__device__ float g_h[(size_t)N_NODES * D];
__device__ float g_sum[D];
__device__ float g_sumsq[D];
__device__ int   g_idx_is64;
__device__ __nv_bfloat16 gW_hi[256 * 128];   // rows 0-127 W_root, 128-255 W_rel
__device__ __nv_bfloat16 gW_lo[256 * 128];

// ---------------- helpers ----------------
__device__ __forceinline__ uint32_t smem_u32(const void* p) {
    uint32_t a;
    asm("{ .reg .u64 t; cvta.to.shared.u64 t, %1; cvt.u32.u64 %0, t; }"
        : "=r"(a) : "l"(p));
    return a;
}
__device__ __forceinline__ void ldsm_x4_t(uint32_t& r0, uint32_t& r1,
                                          uint32_t& r2, uint32_t& r3, uint32_t a) {
    asm volatile("ldmatrix.sync.aligned.m8n8.x4.trans.shared.b16 {%0,%1,%2,%3}, [%4];"
                 : "=r"(r0), "=r"(r1), "=r"(r2), "=r"(r3) : "r"(a));
}
__device__ __forceinline__ void mma_bf16(float* c, const uint32_t* a, const uint32_t* b) {
    asm volatile("mma.sync.aligned.m16n8k16.row.col.f32.bf16.bf16.f32 "
                 "{%0,%1,%2,%3}, {%4,%5,%6,%7}, {%8,%9}, {%0,%1,%2,%3};"
                 : "+f"(c[0]), "+f"(c[1]), "+f"(c[2]), "+f"(c[3])
                 : "r"(a[0]), "r"(a[1]), "r"(a[2]), "r"(a[3]),
                   "r"(b[0]), "r"(b[1]));
}
__device__ __forceinline__ void split_bf(float2 v, uint32_t& hi, uint32_t& lo) {
    __nv_bfloat16 h0 = __float2bfloat16(v.x);
    __nv_bfloat16 h1 = __float2bfloat16(v.y);
    __nv_bfloat162 hp = __halves2bfloat162(h0, h1);
    __nv_bfloat162 lp = __halves2bfloat162(
        __float2bfloat16(v.x - __bfloat162float(h0)),
        __float2bfloat16(v.y - __bfloat162float(h1)));
    hi = *(uint32_t*)&hp;
    lo = *(uint32_t*)&lp;
}
__device__ __forceinline__ void red_add_v4(float* addr, float4 v) {
    asm volatile("red.global.add.v4.f32 [%0], {%1, %2, %3, %4};"
                 :: "l"(addr), "f"(v.x), "f"(v.y), "f"(v.z), "f"(v.w)
                 : "memory");
}

// smem layout (byte offsets in dynamic smem)
#define B_HI   0             // 128 rows * 272 B
#define B_LO   34816
#define SM_BIAS 69632        // 128 f32
#define SM_SSUM 70144        // 128 f32
#define SM_SSQ  70656        // 128 f32
#define SMEMSZ  71168

// ---------------- kernel 0: detect edge_index dtype ----------------
__global__ void probe_kernel(const int* __restrict__ e) {
    __shared__ int nz;
    if (threadIdx.x == 0) nz = 0;
    __syncthreads();
    int v = e[threadIdx.x * 2 + 1];
    if (v != 0) atomicAdd(&nz, 1);
    __syncthreads();
    if (threadIdx.x == 0) g_idx_is64 = (nz == 0) ? 1 : 0;
}

// ---------------- kernel 1: zero aggr + stats ----------------
__global__ void zero_kernel() {
    int idx = blockIdx.x * blockDim.x + threadIdx.x;
    const int n4 = (N_NODES * D) / 4;
    if (idx < n4) ((float4*)g_aggr)[idx] = make_float4(0.f, 0.f, 0.f, 0.f);
    if (blockIdx.x == 0 && threadIdx.x < D) {
        g_sum[threadIdx.x] = 0.f;
        g_sumsq[threadIdx.x] = 0.f;
    }
}

// ---------------- kernel 2: convert weights to bf16 hi/lo (once) ----------
__global__ void wconv_kernel(const float* __restrict__ W_root,
                             const float* __restrict__ W_rel) {
    int idx = blockIdx.x * blockDim.x + threadIdx.x;   // 8192 threads
#pragma unroll
    for (int p = idx; p < 16384; p += 8192) {
        int k = p >> 6;
        int n2 = (p & 63) * 2;
        const float* W = (k < 128) ? (W_root + k * 128 + n2)
                                   : (W_rel + (k - 128) * 128 + n2);
        float2 v = *(const float2*)W;
        uint32_t hi, lo;
        split_bf(v, hi, lo);
        *(uint32_t*)((char*)gW_hi + (size_t)(k * 128 + n2) * 2) = hi;
        *(uint32_t*)((char*)gW_lo + (size_t)(k * 128 + n2) * 2) = lo;
    }
}

// ---------------- kernel 3: scatter (standalone, high occupancy) ----------
#define EB 8                    // edges per warp-iteration
#define SC_BLOCKS 592           // 4 per SM

__global__ void __launch_bounds__(256, 4)
scatter_kernel(const void* __restrict__ edge_index,
               const float* __restrict__ x) {
    const int wid = threadIdx.x >> 5;
    const int lane = threadIdx.x & 31;
    const int wglob = blockIdx.x * 8 + wid;
    const int NW = SC_BLOCKS * 8;
    const bool is64 = (g_idx_is64 != 0);

#pragma unroll 1
    for (int it = 0; ; it++) {
        int e0 = (wglob + it * NW) * EB;
        if (e0 >= N_EDGES) break;
        int s[EB], d[EB];
        if (is64) {
            const long long* e = (const long long*)edge_index;
#pragma unroll
            for (int j = 0; j < EB; j++) {
                s[j] = (int)e[e0 + j];
                d[j] = (int)e[N_EDGES + e0 + j];
            }
        } else {
            const int* e = (const int*)edge_index;
            int4 sv0 = *(const int4*)(e + e0);
            int4 sv1 = *(const int4*)(e + e0 + 4);
            int4 dv0 = *(const int4*)(e + N_EDGES + e0);
            int4 dv1 = *(const int4*)(e + N_EDGES + e0 + 4);
            s[0] = sv0.x; s[1] = sv0.y; s[2] = sv0.z; s[3] = sv0.w;
            s[4] = sv1.x; s[5] = sv1.y; s[6] = sv1.z; s[7] = sv1.w;
            d[0] = dv0.x; d[1] = dv0.y; d[2] = dv0.z; d[3] = dv0.w;
            d[4] = dv1.x; d[5] = dv1.y; d[6] = dv1.z; d[7] = dv1.w;
        }
        int cnt = N_EDGES - e0; if (cnt > EB) cnt = EB;
        float4 v[EB];
#pragma unroll
        for (int j = 0; j < EB; j++) {
            bool ok = (j < cnt) && ((unsigned)s[j] < N_NODES);
            v[j] = ok ? ((const float4*)(x + (size_t)s[j] * D))[lane]
                      : make_float4(0.f, 0.f, 0.f, 0.f);
        }
#pragma unroll
        for (int j = 0; j < EB; j++) {
            if ((j < cnt) && ((unsigned)s[j] < N_NODES) && ((unsigned)d[j] < N_NODES))
                red_add_v4(g_aggr + (size_t)d[j] * D + lane * 4, v[j]);
        }
    }
}

// ---------------- kernel 4: K=256 GEMM + bias + BN stats ------------------
// h = x@W_root + aggr@W_rel + b_rel ; accumulators register-resident across
// both K halves; B smem refilled between halves. Direct store (no RMW).
__global__ void __launch_bounds__(256, 2)
gemmAB_kernel(const float* __restrict__ x, const float* __restrict__ b_rel) {
    extern __shared__ char smem[];
    const uint32_t sb = smem_u32(smem);
    const int tid = threadIdx.x;
    const int w = tid >> 5;
    const int lid = tid & 31;
    const int m0 = blockIdx.x * 128;

    if (tid < 128) {
        ((float*)(smem + SM_BIAS))[tid] = b_rel[tid];
        ((float*)(smem + SM_SSUM))[tid] = 0.f;
        ((float*)(smem + SM_SSQ))[tid]  = 0.f;
    }

    float acc[16][4];
#pragma unroll
    for (int q = 0; q < 16; q++)
#pragma unroll
        for (int c = 0; c < 4; c++) acc[q][c] = 0.f;

    const int r = lid >> 2;
    const int cq = (lid & 3) * 2;
    const int m = m0 + w * 16 + r;
    const bool v0 = m < N_NODES;
    const bool v1 = (m + 8) < N_NODES;
    const float2 fz = make_float2(0.f, 0.f);

#pragma unroll 1
    for (int half = 0; half < 2; half++) {
        // fill B smem with W_root (half 0) or W_rel (half 1)
#pragma unroll
        for (int i = 0; i < 8; i++) {
            int ch = tid + i * 256;
            int row = ch >> 4, c16 = ch & 15;
            size_t gsrc = (size_t)((half * 128 + row) * 128 + c16 * 8) * 2;
            *(uint4*)(smem + B_HI + row * 272 + c16 * 16) =
                *(const uint4*)((const char*)gW_hi + gsrc);
            *(uint4*)(smem + B_LO + row * 272 + c16 * 16) =
                *(const uint4*)((const char*)gW_lo + gsrc);
        }
        __syncthreads();

        const float* A = half ? g_aggr : x;
        const float* pr0 = A + (size_t)m * D + cq;
        const float* pr1 = A + (size_t)(m + 8) * D + cq;

#pragma unroll
        for (int s = 0; s < 8; s++) {          // K = 128 per half
            const int ko = s * 16;
            float2 x00 = v0 ? *(const float2*)(pr0 + ko) : fz;
            float2 x10 = v1 ? *(const float2*)(pr1 + ko) : fz;
            float2 x01 = v0 ? *(const float2*)(pr0 + ko + 8) : fz;
            float2 x11 = v1 ? *(const float2*)(pr1 + ko + 8) : fz;
            uint32_t ah[4], al[4];
            split_bf(x00, ah[0], al[0]);
            split_bf(x10, ah[1], al[1]);
            split_bf(x01, ah[2], al[2]);
            split_bf(x11, ah[3], al[3]);

            const uint32_t rowa = sb + (uint32_t)((s * 16 + (lid & 15)) * 272
                                                  + (lid >> 4) * 16);
#pragma unroll
            for (int q8 = 0; q8 < 8; q8++) {   // 16-col blocks
                uint32_t bh[4], bl[4];
                uint32_t ba = rowa + (uint32_t)(q8 * 32);
                ldsm_x4_t(bh[0], bh[1], bh[2], bh[3], ba + B_HI);
                ldsm_x4_t(bl[0], bl[1], bl[2], bl[3], ba + B_LO);
                float* c0 = acc[q8 * 2];
                float* c1 = acc[q8 * 2 + 1];
                mma_bf16(c0, ah, bh);
                mma_bf16(c0, ah, bl);
                mma_bf16(c0, al, bh);
                mma_bf16(c1, ah, bh + 2);
                mma_bf16(c1, ah, bl + 2);
                mma_bf16(c1, al, bh + 2);
            }
        }
        __syncthreads();   // before refill / epilogue
    }

    // ---- epilogue: bias + direct store + BN stats (shuffle-reduced) ----
    const float* bs = (const float*)(smem + SM_BIAS);
    float* ssum = (float*)(smem + SM_SSUM);
    float* ssq  = (float*)(smem + SM_SSQ);
#pragma unroll
    for (int q = 0; q < 16; q++) {
        int n = q * 8 + cq;
        float b0 = bs[n], b1 = bs[n + 1];
        float s0 = 0.f, s1 = 0.f, q0 = 0.f, q1 = 0.f;
        if (v0) {
            float2 o = make_float2(acc[q][0] + b0, acc[q][1] + b1);
            *(float2*)(g_h + (size_t)m * D + n) = o;
            s0 += o.x; s1 += o.y;
            q0 += o.x * o.x; q1 += o.y * o.y;
        }
        if (v1) {
            float2 o = make_float2(acc[q][2] + b0, acc[q][3] + b1);
            *(float2*)(g_h + (size_t)(m + 8) * D + n) = o;
            s0 += o.x; s1 += o.y;
            q0 += o.x * o.x; q1 += o.y * o.y;
        }
#pragma unroll
        for (int mk = 4; mk <= 16; mk <<= 1) {
            s0 += __shfl_xor_sync(0xffffffffu, s0, mk);
            s1 += __shfl_xor_sync(0xffffffffu, s1, mk);
            q0 += __shfl_xor_sync(0xffffffffu, q0, mk);
            q1 += __shfl_xor_sync(0xffffffffu, q1, mk);
        }
        if ((lid >> 2) == 0) {
            atomicAdd(&ssum[n],     s0);
            atomicAdd(&ssum[n + 1], s1);
            atomicAdd(&ssq[n],      q0);
            atomicAdd(&ssq[n + 1],  q1);
        }
    }
    __syncthreads();
    if (tid < 128) {
        atomicAdd(&g_sum[tid],   ssum[tid]);
        atomicAdd(&g_sumsq[tid], ssq[tid]);
    }
}

// ---------------- fused finalize + normalize + ReLU ----------------
__global__ void norm_kernel(const float* __restrict__ gamma,
                            const float* __restrict__ beta,
                            float* __restrict__ out) {
    __shared__ float ssc[D], ssh[D];
    int t = threadIdx.x;
    if (t < D) {
        float inv_n = 1.0f / (float)N_NODES;
        float mean = g_sum[t] * inv_n;
        float var = g_sumsq[t] * inv_n - mean * mean;
        float sc = gamma[t] * rsqrtf(var + EPS);
        ssc[t] = sc;
        ssh[t] = beta[t] - mean * sc;
    }
    __syncthreads();
    int idx = blockIdx.x * blockDim.x + t;
    const int n4 = (N_NODES * D) / 4;
    if (idx >= n4) return;
    int c4 = (idx & (D / 4 - 1)) * 4;
    float4 h = ((const float4*)g_h)[idx];
    float4 o;
    o.x = fmaxf(h.x * ssc[c4 + 0] + ssh[c4 + 0], 0.f);
    o.y = fmaxf(h.y * ssc[c4 + 1] + ssh[c4 + 1], 0.f);
    o.z = fmaxf(h.z * ssc[c4 + 2] + ssh[c4 + 2], 0.f);
    o.w = fmaxf(h.w * ssc[c4 + 3] + ssh[c4 + 3], 0.f);
    ((float4*)out)[idx] = o;
}

// ---------------- launch ----------------
extern "C" void kernel_launch(void* const* d_in, const int* in_sizes, int n_in,
                              void* d_out, int out_size) {
    const float* x      = (const float*)d_in[0];
    const void*  eidx   = d_in[1];
    const float* W_root = (const float*)d_in[2];
    const float* W_rel  = (const float*)d_in[3];
    const float* b_rel  = (const float*)d_in[4];
    const float* gamma  = (const float*)d_in[5];
    const float* beta   = (const float*)d_in[6];
    float*       out    = (float*)d_out;

    cudaFuncSetAttribute(gemmAB_kernel,
                         cudaFuncAttributeMaxDynamicSharedMemorySize, SMEMSZ);

    probe_kernel<<<1, 64>>>((const int*)eidx);

    const int n4 = (N_NODES * D) / 4;
    zero_kernel<<<(n4 + 255) / 256, 256>>>();

    wconv_kernel<<<32, 256>>>(W_root, W_rel);

    scatter_kernel<<<SC_BLOCKS, 256>>>(eidx, x);

    gemmAB_kernel<<<(N_NODES + 127) / 128, 256, SMEMSZ>>>(x, b_rel);

    norm_kernel<<<(n4 + 255) / 256, 256>>>(gamma, beta, out);
}

// round 10
// speedup vs baseline: 1.4944x; 1.0780x over previous
#include <cuda_runtime.h>
#include <cuda_fp16.h>
#include <cstdint>

#define N_NODES 100000
#define N_EDGES 1600000
#define D 128
#define EPS 1e-5f

// ---------------- scratch ----------------
__device__ float g_aggr[(size_t)N_NODES * D];
__device__ float g_h[(size_t)N_NODES * D];
__device__ float g_sum[D];
__device__ float g_sumsq[D];
__device__ int   g_idx_is64;
__device__ __half gW_h[256 * 128];   // rows 0-127 W_root, 128-255 W_rel (fp16)

// ---------------- helpers ----------------
__device__ __forceinline__ uint32_t smem_u32(const void* p) {
    uint32_t a;
    asm("{ .reg .u64 t; cvta.to.shared.u64 t, %1; cvt.u32.u64 %0, t; }"
        : "=r"(a) : "l"(p));
    return a;
}
__device__ __forceinline__ void ldsm_x4_t(uint32_t& r0, uint32_t& r1,
                                          uint32_t& r2, uint32_t& r3, uint32_t a) {
    asm volatile("ldmatrix.sync.aligned.m8n8.x4.trans.shared.b16 {%0,%1,%2,%3}, [%4];"
                 : "=r"(r0), "=r"(r1), "=r"(r2), "=r"(r3) : "r"(a));
}
__device__ __forceinline__ void mma_f16(float* c, const uint32_t* a, const uint32_t* b) {
    asm volatile("mma.sync.aligned.m16n8k16.row.col.f32.f16.f16.f32 "
                 "{%0,%1,%2,%3}, {%4,%5,%6,%7}, {%8,%9}, {%0,%1,%2,%3};"
                 : "+f"(c[0]), "+f"(c[1]), "+f"(c[2]), "+f"(c[3])
                 : "r"(a[0]), "r"(a[1]), "r"(a[2]), "r"(a[3]),
                   "r"(b[0]), "r"(b[1]));
}
// fp16 hi/lo split of two fp32 values (22-bit effective mantissa)
__device__ __forceinline__ void split_h(float2 v, uint32_t& hi, uint32_t& lo) {
    __half h0 = __float2half_rn(v.x);
    __half h1 = __float2half_rn(v.y);
    __half2 hp = __halves2half2(h0, h1);
    __half2 lp = __halves2half2(__float2half_rn(v.x - __half2float(h0)),
                                __float2half_rn(v.y - __half2float(h1)));
    hi = *(uint32_t*)&hp;
    lo = *(uint32_t*)&lp;
}
__device__ __forceinline__ void red_add_v4(float* addr, float4 v) {
    asm volatile("red.global.add.v4.f32 [%0], {%1, %2, %3, %4};"
                 :: "l"(addr), "f"(v.x), "f"(v.y), "f"(v.z), "f"(v.w)
                 : "memory");
}

// smem layout (byte offsets in dynamic smem)
#define B_HI   0             // 128 rows * 272 B
#define SM_BIAS 34816        // 128 f32
#define SM_SSUM 35328        // 128 f32
#define SM_SSQ  35840        // 128 f32
#define SMEMSZ  36352

// ---------------- kernel 0: detect edge_index dtype ----------------
__global__ void probe_kernel(const int* __restrict__ e) {
    __shared__ int nz;
    if (threadIdx.x == 0) nz = 0;
    __syncthreads();
    int v = e[threadIdx.x * 2 + 1];
    if (v != 0) atomicAdd(&nz, 1);
    __syncthreads();
    if (threadIdx.x == 0) g_idx_is64 = (nz == 0) ? 1 : 0;
}

// ---------------- kernel 1: zero aggr + stats ----------------
__global__ void zero_kernel() {
    int idx = blockIdx.x * blockDim.x + threadIdx.x;
    const int n4 = (N_NODES * D) / 4;
    if (idx < n4) ((float4*)g_aggr)[idx] = make_float4(0.f, 0.f, 0.f, 0.f);
    if (blockIdx.x == 0 && threadIdx.x < D) {
        g_sum[threadIdx.x] = 0.f;
        g_sumsq[threadIdx.x] = 0.f;
    }
}

// ---------------- kernel 2: convert weights to fp16 (once) ----------------
__global__ void wconv_kernel(const float* __restrict__ W_root,
                             const float* __restrict__ W_rel) {
    int idx = blockIdx.x * blockDim.x + threadIdx.x;   // 8192 threads
#pragma unroll
    for (int p = idx; p < 16384; p += 8192) {
        int k = p >> 6;
        int n2 = (p & 63) * 2;
        const float* W = (k < 128) ? (W_root + k * 128 + n2)
                                   : (W_rel + (k - 128) * 128 + n2);
        float2 v = *(const float2*)W;
        __half2 h = __halves2half2(__float2half_rn(v.x), __float2half_rn(v.y));
        *(uint32_t*)((char*)gW_h + (size_t)(k * 128 + n2) * 2) = *(uint32_t*)&h;
    }
}

// ---------------- kernel 3: scatter (standalone, high occupancy) ----------
#define EB 8                    // edges per warp-iteration
#define SC_BLOCKS 592           // 4 per SM

__global__ void __launch_bounds__(256, 4)
scatter_kernel(const void* __restrict__ edge_index,
               const float* __restrict__ x) {
    const int wid = threadIdx.x >> 5;
    const int lane = threadIdx.x & 31;
    const int wglob = blockIdx.x * 8 + wid;
    const int NW = SC_BLOCKS * 8;
    const bool is64 = (g_idx_is64 != 0);

#pragma unroll 1
    for (int it = 0; ; it++) {
        int e0 = (wglob + it * NW) * EB;
        if (e0 >= N_EDGES) break;
        int s[EB], d[EB];
        if (is64) {
            const long long* e = (const long long*)edge_index;
#pragma unroll
            for (int j = 0; j < EB; j++) {
                s[j] = (int)e[e0 + j];
                d[j] = (int)e[N_EDGES + e0 + j];
            }
        } else {
            const int* e = (const int*)edge_index;
            int4 sv0 = *(const int4*)(e + e0);
            int4 sv1 = *(const int4*)(e + e0 + 4);
            int4 dv0 = *(const int4*)(e + N_EDGES + e0);
            int4 dv1 = *(const int4*)(e + N_EDGES + e0 + 4);
            s[0] = sv0.x; s[1] = sv0.y; s[2] = sv0.z; s[3] = sv0.w;
            s[4] = sv1.x; s[5] = sv1.y; s[6] = sv1.z; s[7] = sv1.w;
            d[0] = dv0.x; d[1] = dv0.y; d[2] = dv0.z; d[3] = dv0.w;
            d[4] = dv1.x; d[5] = dv1.y; d[6] = dv1.z; d[7] = dv1.w;
        }
        int cnt = N_EDGES - e0; if (cnt > EB) cnt = EB;
        float4 v[EB];
#pragma unroll
        for (int j = 0; j < EB; j++) {
            bool ok = (j < cnt) && ((unsigned)s[j] < N_NODES);
            v[j] = ok ? ((const float4*)(x + (size_t)s[j] * D))[lane]
                      : make_float4(0.f, 0.f, 0.f, 0.f);
        }
#pragma unroll
        for (int j = 0; j < EB; j++) {
            if ((j < cnt) && ((unsigned)s[j] < N_NODES) && ((unsigned)d[j] < N_NODES))
                red_add_v4(g_aggr + (size_t)d[j] * D + lane * 4, v[j]);
        }
    }
}

// ---------------- kernel 4: K=256 GEMM + bias + BN stats ------------------
// h = x@W_root + aggr@W_rel + b_rel
// fp16 asymmetric split: A = ah + al (both fp16), B = fp16(W).
// Error: dropped a*(w - fp16(w)) term ~ 2^-12 relative.
__global__ void __launch_bounds__(256, 2)
gemmAB_kernel(const float* __restrict__ x, const float* __restrict__ b_rel) {
    extern __shared__ char smem[];
    const uint32_t sb = smem_u32(smem);
    const int tid = threadIdx.x;
    const int w = tid >> 5;
    const int lid = tid & 31;
    const int m0 = blockIdx.x * 128;

    if (tid < 128) {
        ((float*)(smem + SM_BIAS))[tid] = b_rel[tid];
        ((float*)(smem + SM_SSUM))[tid] = 0.f;
        ((float*)(smem + SM_SSQ))[tid]  = 0.f;
    }

    float acc[16][4];
#pragma unroll
    for (int q = 0; q < 16; q++)
#pragma unroll
        for (int c = 0; c < 4; c++) acc[q][c] = 0.f;

    const int r = lid >> 2;
    const int cq = (lid & 3) * 2;
    const int m = m0 + w * 16 + r;
    const bool v0 = m < N_NODES;
    const bool v1 = (m + 8) < N_NODES;
    const float2 fz = make_float2(0.f, 0.f);

#pragma unroll 1
    for (int half = 0; half < 2; half++) {
        // fill B smem with fp16 W_root (half 0) or W_rel (half 1)
#pragma unroll
        for (int i = 0; i < 8; i++) {
            int ch = tid + i * 256;
            int row = ch >> 4, c16 = ch & 15;
            size_t gsrc = (size_t)((half * 128 + row) * 128 + c16 * 8) * 2;
            *(uint4*)(smem + B_HI + row * 272 + c16 * 16) =
                *(const uint4*)((const char*)gW_h + gsrc);
        }
        __syncthreads();

        const float* A = half ? g_aggr : x;
        const float* pr0 = A + (size_t)m * D + cq;
        const float* pr1 = A + (size_t)(m + 8) * D + cq;

#pragma unroll
        for (int s = 0; s < 8; s++) {          // K = 128 per half
            const int ko = s * 16;
            float2 x00 = v0 ? *(const float2*)(pr0 + ko) : fz;
            float2 x10 = v1 ? *(const float2*)(pr1 + ko) : fz;
            float2 x01 = v0 ? *(const float2*)(pr0 + ko + 8) : fz;
            float2 x11 = v1 ? *(const float2*)(pr1 + ko + 8) : fz;
            uint32_t ah[4], al[4];
            split_h(x00, ah[0], al[0]);
            split_h(x10, ah[1], al[1]);
            split_h(x01, ah[2], al[2]);
            split_h(x11, ah[3], al[3]);

            const uint32_t rowa = sb + (uint32_t)((s * 16 + (lid & 15)) * 272
                                                  + (lid >> 4) * 16);
#pragma unroll
            for (int q8 = 0; q8 < 8; q8++) {   // 16-col blocks
                uint32_t bh[4];
                ldsm_x4_t(bh[0], bh[1], bh[2], bh[3],
                          rowa + (uint32_t)(q8 * 32) + B_HI);
                float* c0 = acc[q8 * 2];
                float* c1 = acc[q8 * 2 + 1];
                mma_f16(c0, ah, bh);
                mma_f16(c0, al, bh);
                mma_f16(c1, ah, bh + 2);
                mma_f16(c1, al, bh + 2);
            }
        }
        __syncthreads();   // before refill / epilogue
    }

    // ---- epilogue: bias + direct store + BN stats (shuffle-reduced) ----
    const float* bs = (const float*)(smem + SM_BIAS);
    float* ssum = (float*)(smem + SM_SSUM);
    float* ssq  = (float*)(smem + SM_SSQ);
#pragma unroll
    for (int q = 0; q < 16; q++) {
        int n = q * 8 + cq;
        float b0 = bs[n], b1 = bs[n + 1];
        float s0 = 0.f, s1 = 0.f, q0 = 0.f, q1 = 0.f;
        if (v0) {
            float2 o = make_float2(acc[q][0] + b0, acc[q][1] + b1);
            *(float2*)(g_h + (size_t)m * D + n) = o;
            s0 += o.x; s1 += o.y;
            q0 += o.x * o.x; q1 += o.y * o.y;
        }
        if (v1) {
            float2 o = make_float2(acc[q][2] + b0, acc[q][3] + b1);
            *(float2*)(g_h + (size_t)(m + 8) * D + n) = o;
            s0 += o.x; s1 += o.y;
            q0 += o.x * o.x; q1 += o.y * o.y;
        }
#pragma unroll
        for (int mk = 4; mk <= 16; mk <<= 1) {
            s0 += __shfl_xor_sync(0xffffffffu, s0, mk);
            s1 += __shfl_xor_sync(0xffffffffu, s1, mk);
            q0 += __shfl_xor_sync(0xffffffffu, q0, mk);
            q1 += __shfl_xor_sync(0xffffffffu, q1, mk);
        }
        if ((lid >> 2) == 0) {
            atomicAdd(&ssum[n],     s0);
            atomicAdd(&ssum[n + 1], s1);
            atomicAdd(&ssq[n],      q0);
            atomicAdd(&ssq[n + 1],  q1);
        }
    }
    __syncthreads();
    if (tid < 128) {
        atomicAdd(&g_sum[tid],   ssum[tid]);
        atomicAdd(&g_sumsq[tid], ssq[tid]);
    }
}

// ---------------- fused finalize + normalize + ReLU ----------------
__global__ void norm_kernel(const float* __restrict__ gamma,
                            const float* __restrict__ beta,
                            float* __restrict__ out) {
    __shared__ float ssc[D], ssh[D];
    int t = threadIdx.x;
    if (t < D) {
        float inv_n = 1.0f / (float)N_NODES;
        float mean = g_sum[t] * inv_n;
        float var = g_sumsq[t] * inv_n - mean * mean;
        float sc = gamma[t] * rsqrtf(var + EPS);
        ssc[t] = sc;
        ssh[t] = beta[t] - mean * sc;
    }
    __syncthreads();
    int idx = blockIdx.x * blockDim.x + t;
    const int n4 = (N_NODES * D) / 4;
    if (idx >= n4) return;
    int c4 = (idx & (D / 4 - 1)) * 4;
    float4 h = ((const float4*)g_h)[idx];
    float4 o;
    o.x = fmaxf(h.x * ssc[c4 + 0] + ssh[c4 + 0], 0.f);
    o.y = fmaxf(h.y * ssc[c4 + 1] + ssh[c4 + 1], 0.f);
    o.z = fmaxf(h.z * ssc[c4 + 2] + ssh[c4 + 2], 0.f);
    o.w = fmaxf(h.w * ssc[c4 + 3] + ssh[c4 + 3], 0.f);
    ((float4*)out)[idx] = o;
}

// ---------------- launch ----------------
extern "C" void kernel_launch(void* const* d_in, const int* in_sizes, int n_in,
                              void* d_out, int out_size) {
    const float* x      = (const float*)d_in[0];
    const void*  eidx   = d_in[1];
    const float* W_root = (const float*)d_in[2];
    const float* W_rel  = (const float*)d_in[3];
    const float* b_rel  = (const float*)d_in[4];
    const float* gamma  = (const float*)d_in[5];
    const float* beta   = (const float*)d_in[6];
    float*       out    = (float*)d_out;

    cudaFuncSetAttribute(gemmAB_kernel,
                         cudaFuncAttributeMaxDynamicSharedMemorySize, SMEMSZ);

    probe_kernel<<<1, 64>>>((const int*)eidx);

    const int n4 = (N_NODES * D) / 4;
    zero_kernel<<<(n4 + 255) / 256, 256>>>();

    wconv_kernel<<<32, 256>>>(W_root, W_rel);

    scatter_kernel<<<SC_BLOCKS, 256>>>(eidx, x);

    gemmAB_kernel<<<(N_NODES + 127) / 128, 256, SMEMSZ>>>(x, b_rel);

    norm_kernel<<<(n4 + 255) / 256, 256>>>(gamma, beta, out);
}